// round 4
// baseline (speedup 1.0000x reference)
#include <cuda_runtime.h>

// ProbabilisticPatching: Gumbel-top-k (k=32) over 512 features per (batch,patch) row.
// RNG: JAX threefry PARTITIONABLE path: bits32[i] = xor-halves of tf2x32(key=0,(0,i)).
// R4: threshold-based selection (no per-element logf), IMAD-forced mix adds,
//     lazy exact scoring only for boundary candidates. Output bit-identical to R3.

#define NP 64
#define NF 512
#define NB 2048
#define NROWS (NB * NP)   // 131072

__device__ float    g_logp[NP * NF];
__device__ unsigned g_thr [NP * NF];   // min (bits>>9) for score > pivot; 1<<23 = never

// ---------------- Threefry-2x32, key = (0,0); mix-adds forced to IMAD ----------------
__device__ __forceinline__ unsigned tf_bits32(unsigned i, unsigned one) {
    const unsigned ks2 = 0x1BD11BDAu;
    unsigned x0 = 0u, x1 = i;
#define TF_RND(r) { x0 = x0 * one + x1; x1 = __funnelshift_l(x1, x1, r); x1 ^= x0; }
    TF_RND(13) TF_RND(15) TF_RND(26) TF_RND(6)
    /* x0 += ks1(0) */            x1 += ks2 + 1u;
    TF_RND(17) TF_RND(29) TF_RND(16) TF_RND(24)
    x0 += ks2;                    x1 += 2u;
    TF_RND(13) TF_RND(15) TF_RND(26) TF_RND(6)
    /* x0 += ks0(0) */            x1 += 3u;
    TF_RND(17) TF_RND(29) TF_RND(16) TF_RND(24)
    /* x0 += ks1(0) */            x1 += ks2 + 4u;
    TF_RND(13) TF_RND(15) TF_RND(26) TF_RND(6)
    x0 += ks2;                    x1 += 5u;
#undef TF_RND
    return x0 ^ x1;
}

// order-preserving float -> uint mapping
__device__ __forceinline__ unsigned orderable(float f) {
    unsigned b = __float_as_uint(f);
    unsigned m = (unsigned)(((int)b) >> 31) | 0x80000000u;
    return b ^ m;
}

// JAX uniform(1e-20, 1) from raw bits, then standard Gumbel (accurate logf).
__device__ __forceinline__ float gumbel_from_bits(unsigned bits) {
    float f = __uint_as_float((bits >> 9) | 0x3f800000u) - 1.0f;
    float u = (f > 0.0f) ? f : 1e-20f;
    return -logf(-logf(u));
}

__device__ __forceinline__ float gumbel_from_m23(unsigned m23) {
    float f = __uint_as_float(m23 | 0x3f800000u) - 1.0f;
    float u = (f > 0.0f) ? f : 1e-20f;
    return -logf(-logf(u));
}

// ---------------- prep: logp (IDENTICAL math to R3) + pivot + per-f bit thresholds ----
__global__ void prep_kernel(const float* __restrict__ w) {
    int p = blockIdx.x;
    int t = threadIdx.x;
    int lane = t & 31, wid = t >> 5;
    float wv = w[p * NF + t];

    __shared__ float sm[16];
    __shared__ float ws[16];
    __shared__ float s_total;
    __shared__ float red[16];

    // exact row max (order-independent)
    float m = wv;
    for (int off = 16; off; off >>= 1)
        m = fmaxf(m, __shfl_xor_sync(0xffffffffu, m, off));
    if (lane == 0) sm[wid] = m;
    __syncthreads();
    float mall = sm[0];
    #pragma unroll
    for (int i = 1; i < 16; ++i) mall = fmaxf(mall, sm[i]);

    // sum(exp(shifted)) — DO NOT CHANGE ORDER (fixes passing rel_err)
    float e = expf(wv - mall);
    float v = e;
    v += __shfl_down_sync(0xffffffffu, v, 16);
    v += __shfl_down_sync(0xffffffffu, v, 8);
    v += __shfl_down_sync(0xffffffffu, v, 4);
    v += __shfl_down_sync(0xffffffffu, v, 2);
    v += __shfl_down_sync(0xffffffffu, v, 1);
    if (lane == 0) ws[wid] = v;
    __syncthreads();
    if (wid == 0) {
        float vv = (lane < 16) ? ws[lane] : 0.0f;
        vv += __shfl_down_sync(0xffffffffu, vv, 8);
        vv += __shfl_down_sync(0xffffffffu, vv, 4);
        vv += __shfl_down_sync(0xffffffffu, vv, 2);
        vv += __shfl_down_sync(0xffffffffu, vv, 1);
        if (lane == 0) s_total = vv;
    }
    __syncthreads();

    float L  = logf(s_total);
    float lp = (wv - mall) - L;
    g_logp[p * NF + t] = lp;

    // pivot: solve sum_f P(lp_f + G > piv) = 38  (over-select; mask is pivot-independent)
    float lo = -40.0f, hi = 40.0f;
    for (int it = 0; it < 35; ++it) {
        float mid = 0.5f * (lo + hi);
        float pr = 1.0f - expf(-expf(lp - mid));
        float sv = pr;
        for (int off = 16; off; off >>= 1)
            sv += __shfl_xor_sync(0xffffffffu, sv, off);
        if (lane == 0) red[wid] = sv;
        __syncthreads();
        float tot = 0.0f;
        #pragma unroll
        for (int i = 0; i < 16; ++i) tot += red[i];
        __syncthreads();
        if (tot > 38.0f) lo = mid; else hi = mid;
    }
    float pivot = 0.5f * (lo + hi);   // identical in every thread

    // exact integer threshold: smallest M in [0, 2^23] with lp + g(M) > pivot.
    // lp + g(M) is monotone nondecreasing in M, so binary search is exact.
    unsigned tlo = 0u, thi = 1u << 23;
    while (tlo < thi) {
        unsigned mid = (tlo + thi) >> 1;
        if (lp + gumbel_from_m23(mid) > pivot) thi = mid; else tlo = mid + 1;
    }
    g_thr[p * NF + t] = tlo;
}

// ---------------- output writer (unchanged) ----------------
__device__ __forceinline__ void write_row(float* __restrict__ out,
                                          const float* __restrict__ x,
                                          unsigned brow, unsigned row,
                                          unsigned m, unsigned lane) {
    const float4* x4 = reinterpret_cast<const float4*>(x + (size_t)brow * NF);
    float4* po = reinterpret_cast<float4*>(out + (size_t)row * 1024);
    float4* mo = reinterpret_cast<float4*>(out + (size_t)row * 1024 + 512);
    #pragma unroll
    for (int j = 0; j < 4; ++j) {
        float4 xv = x4[j * 32 + lane];
        int t0 = 4 * j;
        float m0 = (m >> (t0 + 0)) & 1 ? 1.0f : 0.0f;
        float m1 = (m >> (t0 + 1)) & 1 ? 1.0f : 0.0f;
        float m2 = (m >> (t0 + 2)) & 1 ? 1.0f : 0.0f;
        float m3 = (m >> (t0 + 3)) & 1 ? 1.0f : 0.0f;
        float4 pv = make_float4(xv.x * m0, xv.y * m1, xv.z * m2, xv.w * m3);
        float4 mv = make_float4(m0, m1, m2, m3);
        po[j * 32 + lane] = pv;
        mo[j * 32 + lane] = mv;
    }
}

// One warp per output row. Lane k owns f = 128j + 4k + c (t = 4j + c).
__global__ void __launch_bounds__(256, 3)
main_kernel(const float* __restrict__ x, float* __restrict__ out, unsigned one) {
    unsigned row  = blockIdx.x * 8u + (threadIdx.x >> 5);   // 0..131071
    unsigned lane = threadIdx.x & 31u;
    unsigned p = row & 63u;
    unsigned b = row >> 6;
    unsigned base = row * NF;     // < 2^26

    // thresholds, same f-pattern as write layout
    const uint4* th4 = reinterpret_cast<const uint4*>(g_thr + p * NF);
    unsigned thr[16];
    #pragma unroll
    for (int j = 0; j < 4; ++j) {
        uint4 v = __ldg(&th4[j * 32 + lane]);
        thr[4 * j + 0] = v.x; thr[4 * j + 1] = v.y;
        thr[4 * j + 2] = v.z; thr[4 * j + 3] = v.w;
    }

    // generate bits + threshold-select (no logf on the hot path)
    unsigned s[16];       // raw bits now; overwritten by orderable scores if trimming
    unsigned selm = 0;
    #pragma unroll
    for (int t = 0; t < 16; ++t) {
        unsigned f = ((unsigned)(t >> 2) << 7) + (lane << 2) + (t & 3);
        unsigned bits = tf_bits32(base + f, one);
        s[t] = bits;
        if ((bits >> 9) >= thr[t]) selm |= 1u << t;
    }

    int cnt = __reduce_add_sync(0xffffffffu, __popc(selm));

    if (cnt != 32) {
        if (cnt > 32) {
            // exact scores only for selected elements (~6/warp above 32 + 32)
            #pragma unroll
            for (int t = 0; t < 16; ++t) {
                if (selm & (1u << t)) {
                    unsigned f = ((unsigned)(t >> 2) << 7) + (lane << 2) + (t & 3);
                    float lpv = __ldg(&g_logp[p * NF + f]);
                    s[t] = orderable(lpv + gumbel_from_bits(s[t]));
                }
            }
            // remove (cnt-32) smallest; tie -> remove largest f   (same as R3)
            for (int it = cnt; it > 32; --it) {
                unsigned long long key = ~0ull;
                #pragma unroll
                for (int t = 0; t < 16; ++t) {
                    if (selm & (1u << t)) {
                        unsigned f = ((unsigned)(t >> 2) << 7) + (lane << 2) + (t & 3);
                        unsigned long long k =
                            ((unsigned long long)s[t] << 32) | (511u - f);
                        key = (k < key) ? k : key;
                    }
                }
                for (int off = 16; off; off >>= 1) {
                    unsigned long long o = __shfl_xor_sync(0xffffffffu, key, off);
                    key = (o < key) ? o : key;
                }
                unsigned f = 511u - (unsigned)(key & 0xffffffffu);
                if (((f >> 2) & 31u) == lane)
                    selm &= ~(1u << (((f >> 7) << 2) | (f & 3)));
            }
        } else {
            // rare (~14%): full scores, then add largest unselected   (same as R3)
            const float4* lp4 = reinterpret_cast<const float4*>(g_logp + p * NF);
            #pragma unroll
            for (int j = 0; j < 4; ++j) {
                float4 v = __ldg(&lp4[j * 32 + lane]);
                s[4 * j + 0] = orderable(v.x + gumbel_from_bits(s[4 * j + 0]));
                s[4 * j + 1] = orderable(v.y + gumbel_from_bits(s[4 * j + 1]));
                s[4 * j + 2] = orderable(v.z + gumbel_from_bits(s[4 * j + 2]));
                s[4 * j + 3] = orderable(v.w + gumbel_from_bits(s[4 * j + 3]));
            }
            for (int it = cnt; it < 32; ++it) {
                unsigned long long key = 0ull;
                #pragma unroll
                for (int t = 0; t < 16; ++t) {
                    if (!(selm & (1u << t))) {
                        unsigned f = ((unsigned)(t >> 2) << 7) + (lane << 2) + (t & 3);
                        unsigned long long k =
                            ((unsigned long long)s[t] << 32) | (511u - f);
                        key = (k > key) ? k : key;
                    }
                }
                for (int off = 16; off; off >>= 1) {
                    unsigned long long o = __shfl_xor_sync(0xffffffffu, key, off);
                    key = (o > key) ? o : key;
                }
                unsigned f = 511u - (unsigned)(key & 0xffffffffu);
                if (((f >> 2) & 31u) == lane)
                    selm |= 1u << (((f >> 7) << 2) | (f & 3));
            }
        }
    }

    write_row(out, x, b, row, selm, lane);
}

extern "C" void kernel_launch(void* const* d_in, const int* in_sizes, int n_in,
                              void* d_out, int out_size) {
    const float* x = nullptr;
    const float* w = nullptr;
    for (int i = 0; i < n_in; ++i) {
        if (in_sizes[i] == NB * NF) x = (const float*)d_in[i];
        else if (in_sizes[i] == NP * NF) w = (const float*)d_in[i];
    }
    float* out = (float*)d_out;

    prep_kernel<<<NP, NF>>>(w);
    main_kernel<<<NROWS / 8, 256>>>(x, out, 1u);
}

// round 6
// speedup vs baseline: 1.8711x; 1.8711x over previous
#include <cuda_runtime.h>

// ProbabilisticPatching: Gumbel-top-k (k=32) over 512 features per (batch,patch) row.
// RNG: JAX threefry PARTITIONABLE path: bits32[i] = xor-halves of tf2x32(key=0,(0,i)).
// R5: plain-IADD threefry (R4 IMAD reverted); candidate compaction via ballot into
//     per-warp smem, scoring only compacted candidates (~50/row), rank-based exact
//     top-32 (no iterative shfl extraction). Output bit-identical to R3/R4.

#define NP 64
#define NF 512
#define NB 2048
#define NROWS (NB * NP)   // 131072
#define CAP 96            // per-warp candidate buffer capacity

__device__ float    g_logp [NP * NF];
__device__ unsigned g_thr  [NP * NF];   // min (bits>>9) for score > pivot; 1<<23 = never
__device__ float    g_pivot[NP];

// ---------------- Threefry-2x32, key = (0,0) ----------------
__device__ __forceinline__ unsigned tf_bits32(unsigned i) {
    const unsigned ks2 = 0x1BD11BDAu;
    unsigned x0 = 0u, x1 = i;
#define TF_RND(r) { x0 += x1; x1 = __funnelshift_l(x1, x1, r); x1 ^= x0; }
    TF_RND(13) TF_RND(15) TF_RND(26) TF_RND(6)
    /* x0 += ks1(0) */            x1 += ks2 + 1u;
    TF_RND(17) TF_RND(29) TF_RND(16) TF_RND(24)
    x0 += ks2;                    x1 += 2u;
    TF_RND(13) TF_RND(15) TF_RND(26) TF_RND(6)
    /* x0 += ks0(0) */            x1 += 3u;
    TF_RND(17) TF_RND(29) TF_RND(16) TF_RND(24)
    /* x0 += ks1(0) */            x1 += ks2 + 4u;
    TF_RND(13) TF_RND(15) TF_RND(26) TF_RND(6)
    x0 += ks2;                    x1 += 5u;
#undef TF_RND
    return x0 ^ x1;
}

// order-preserving float -> uint mapping
__device__ __forceinline__ unsigned orderable(float f) {
    unsigned b = __float_as_uint(f);
    unsigned m = (unsigned)(((int)b) >> 31) | 0x80000000u;
    return b ^ m;
}

// JAX uniform(1e-20, 1) from raw bits, then standard Gumbel (accurate logf).
__device__ __forceinline__ float gumbel_from_bits(unsigned bits) {
    float f = __uint_as_float((bits >> 9) | 0x3f800000u) - 1.0f;
    float u = (f > 0.0f) ? f : 1e-20f;
    return -logf(-logf(u));
}

__device__ __forceinline__ float gumbel_from_m23(unsigned m23) {
    float f = __uint_as_float(m23 | 0x3f800000u) - 1.0f;
    float u = (f > 0.0f) ? f : 1e-20f;
    return -logf(-logf(u));
}

// ---------------- prep: logp (IDENTICAL math to R3) + pivot + per-f bit thresholds ----
__global__ void prep_kernel(const float* __restrict__ w) {
    int p = blockIdx.x;
    int t = threadIdx.x;
    int lane = t & 31, wid = t >> 5;
    float wv = w[p * NF + t];

    __shared__ float sm[16];
    __shared__ float ws[16];
    __shared__ float s_total;
    __shared__ float red[16];

    // exact row max (order-independent)
    float m = wv;
    for (int off = 16; off; off >>= 1)
        m = fmaxf(m, __shfl_xor_sync(0xffffffffu, m, off));
    if (lane == 0) sm[wid] = m;
    __syncthreads();
    float mall = sm[0];
    #pragma unroll
    for (int i = 1; i < 16; ++i) mall = fmaxf(mall, sm[i]);

    // sum(exp(shifted)) — DO NOT CHANGE ORDER (fixes passing rel_err)
    float e = expf(wv - mall);
    float v = e;
    v += __shfl_down_sync(0xffffffffu, v, 16);
    v += __shfl_down_sync(0xffffffffu, v, 8);
    v += __shfl_down_sync(0xffffffffu, v, 4);
    v += __shfl_down_sync(0xffffffffu, v, 2);
    v += __shfl_down_sync(0xffffffffu, v, 1);
    if (lane == 0) ws[wid] = v;
    __syncthreads();
    if (wid == 0) {
        float vv = (lane < 16) ? ws[lane] : 0.0f;
        vv += __shfl_down_sync(0xffffffffu, vv, 8);
        vv += __shfl_down_sync(0xffffffffu, vv, 4);
        vv += __shfl_down_sync(0xffffffffu, vv, 2);
        vv += __shfl_down_sync(0xffffffffu, vv, 1);
        if (lane == 0) s_total = vv;
    }
    __syncthreads();

    float L  = logf(s_total);
    float lp = (wv - mall) - L;
    g_logp[p * NF + t] = lp;

    // pivot: solve sum_f P(lp_f + G > piv) = 50 (candidate pool; mask pivot-independent)
    float lo = -40.0f, hi = 40.0f;
    for (int it = 0; it < 35; ++it) {
        float mid = 0.5f * (lo + hi);
        float pr = 1.0f - expf(-expf(lp - mid));
        float sv = pr;
        for (int off = 16; off; off >>= 1)
            sv += __shfl_xor_sync(0xffffffffu, sv, off);
        if (lane == 0) red[wid] = sv;
        __syncthreads();
        float tot = 0.0f;
        #pragma unroll
        for (int i = 0; i < 16; ++i) tot += red[i];
        __syncthreads();
        if (tot > 50.0f) lo = mid; else hi = mid;
    }
    float pivot = 0.5f * (lo + hi);   // identical in every thread

    // exact integer threshold: smallest M in [0, 2^23] with lp + g(M) > pivot.
    unsigned tlo = 0u, thi = 1u << 23;
    while (tlo < thi) {
        unsigned mid = (tlo + thi) >> 1;
        if (lp + gumbel_from_m23(mid) > pivot) thi = mid; else tlo = mid + 1;
    }
    g_thr[p * NF + t] = tlo;
    if (t == 0) g_pivot[p] = pivot;
}

// ---------------- exact iterative selection (FALLBACK only, ~0.3% of rows) ----------
__device__ __forceinline__ unsigned select32(const unsigned s[16], unsigned piv,
                                             unsigned lane) {
    unsigned m = 0;
    int cnt = 0;
    #pragma unroll
    for (int t = 0; t < 16; ++t) {
        if (s[t] > piv) { m |= 1u << t; ++cnt; }
    }
    cnt = __reduce_add_sync(0xffffffffu, cnt);

    if (cnt > 32) {
        for (int it = cnt; it > 32; --it) {
            unsigned long long key = ~0ull;
            #pragma unroll
            for (int t = 0; t < 16; ++t) {
                if (m & (1u << t)) {
                    unsigned f = ((unsigned)(t >> 2) << 7) + (lane << 2) + (t & 3);
                    unsigned long long k =
                        ((unsigned long long)s[t] << 32) | (511u - f);
                    key = (k < key) ? k : key;
                }
            }
            for (int off = 16; off; off >>= 1) {
                unsigned long long o = __shfl_xor_sync(0xffffffffu, key, off);
                key = (o < key) ? o : key;
            }
            unsigned f = 511u - (unsigned)(key & 0xffffffffu);
            if (((f >> 2) & 31u) == lane)
                m &= ~(1u << (((f >> 7) << 2) | (f & 3)));
        }
    } else if (cnt < 32) {
        for (int it = cnt; it < 32; ++it) {
            unsigned long long key = 0ull;
            #pragma unroll
            for (int t = 0; t < 16; ++t) {
                if (!(m & (1u << t))) {
                    unsigned f = ((unsigned)(t >> 2) << 7) + (lane << 2) + (t & 3);
                    unsigned long long k =
                        ((unsigned long long)s[t] << 32) | (511u - f);
                    key = (k > key) ? k : key;
                }
            }
            for (int off = 16; off; off >>= 1) {
                unsigned long long o = __shfl_xor_sync(0xffffffffu, key, off);
                key = (o > key) ? o : key;
            }
            unsigned f = 511u - (unsigned)(key & 0xffffffffu);
            if (((f >> 2) & 31u) == lane)
                m |= 1u << (((f >> 7) << 2) | (f & 3));
        }
    }
    return m;
}

__device__ __forceinline__ void write_row(float* __restrict__ out,
                                          const float* __restrict__ x,
                                          unsigned brow, unsigned row,
                                          unsigned m, unsigned lane) {
    const float4* x4 = reinterpret_cast<const float4*>(x + (size_t)brow * NF);
    float4* po = reinterpret_cast<float4*>(out + (size_t)row * 1024);
    float4* mo = reinterpret_cast<float4*>(out + (size_t)row * 1024 + 512);
    #pragma unroll
    for (int j = 0; j < 4; ++j) {
        float4 xv = x4[j * 32 + lane];
        int t0 = 4 * j;
        float m0 = (m >> (t0 + 0)) & 1 ? 1.0f : 0.0f;
        float m1 = (m >> (t0 + 1)) & 1 ? 1.0f : 0.0f;
        float m2 = (m >> (t0 + 2)) & 1 ? 1.0f : 0.0f;
        float m3 = (m >> (t0 + 3)) & 1 ? 1.0f : 0.0f;
        float4 pv = make_float4(xv.x * m0, xv.y * m1, xv.z * m2, xv.w * m3);
        float4 mv = make_float4(m0, m1, m2, m3);
        po[j * 32 + lane] = pv;
        mo[j * 32 + lane] = mv;
    }
}

// One warp per output row. Lane k owns f = 128j + 4k + c (t = 4j + c).
__global__ void __launch_bounds__(256, 3)
main_kernel(const float* __restrict__ x, float* __restrict__ out) {
    __shared__ unsigned long long keys[8][CAP];
    __shared__ unsigned wmask[8][32];

    unsigned w    = threadIdx.x >> 5;
    unsigned lane = threadIdx.x & 31u;
    unsigned row  = blockIdx.x * 8u + w;    // 0..131071
    unsigned p = row & 63u;
    unsigned b = row >> 6;
    unsigned base = row * NF;               // < 2^26
    unsigned ltmask = (1u << lane) - 1u;

    // thresholds, same f-pattern as write layout
    const uint4* th4 = reinterpret_cast<const uint4*>(g_thr + p * NF);
    unsigned thr[16];
    #pragma unroll
    for (int j = 0; j < 4; ++j) {
        uint4 v = __ldg(&th4[j * 32 + lane]);
        thr[4 * j + 0] = v.x; thr[4 * j + 1] = v.y;
        thr[4 * j + 2] = v.z; thr[4 * j + 3] = v.w;
    }

    // ---- phase 1: generate bits, mark candidates (no logf) ----
    unsigned bits[16];
    unsigned candm = 0;
    #pragma unroll
    for (int t = 0; t < 16; ++t) {
        unsigned f = ((unsigned)(t >> 2) << 7) + (lane << 2) + (t & 3);
        bits[t] = tf_bits32(base + f);
        if ((bits[t] >> 9) >= thr[t]) candm |= 1u << t;
    }

    // ---- compaction: ballot/prefix -> per-warp smem (bits, f) entries ----
    unsigned n = 0;
    #pragma unroll
    for (int t = 0; t < 16; ++t) {
        unsigned bal = __ballot_sync(0xffffffffu, (candm >> t) & 1u);
        if ((candm >> t) & 1u) {
            unsigned slot = n + __popc(bal & ltmask);
            unsigned f = ((unsigned)(t >> 2) << 7) + (lane << 2) + (t & 3);
            if (slot < CAP)
                keys[w][slot] = ((unsigned long long)bits[t] << 32) | f;
        }
        n += __popc(bal);
    }
    __syncwarp();

    unsigned selm;
    if (n >= 32 && n <= CAP) {
        // ---- phase 2: score only compacted candidates (<=3 per lane) ----
        for (unsigned si = lane; si < n; si += 32) {
            unsigned long long e = keys[w][si];
            unsigned bv = (unsigned)(e >> 32);
            unsigned f  = (unsigned)(e & 0x3ffu);
            float lpv = __ldg(&g_logp[p * NF + f]);
            unsigned sc = orderable(lpv + gumbel_from_bits(bv));
            keys[w][si] = ((unsigned long long)sc << 32) | (511u - f);
        }
        wmask[w][lane] = 0u;
        __syncwarp();

        // ---- phase 3: exact rank among candidates; keep rank < 32 ----
        for (unsigned si = lane; si < n; si += 32) {
            unsigned long long k = keys[w][si];
            int rank = 0;
            for (unsigned j = 0; j < n; ++j)
                rank += (keys[w][j] > k) ? 1 : 0;
            if (rank < 32) {
                unsigned f = 511u - (unsigned)(k & 0x3ffu);
                unsigned owner = (f >> 2) & 31u;
                unsigned bit = ((f >> 7) << 2) | (f & 3u);
                atomicOr(&wmask[w][owner], 1u << bit);
            }
        }
        __syncwarp();
        selm = wmask[w][lane];
    } else {
        // ---- fallback (~0.3%): full scores + exact iterative select ----
        const float4* lp4 = reinterpret_cast<const float4*>(g_logp + p * NF);
        unsigned s[16];
        #pragma unroll
        for (int j = 0; j < 4; ++j) {
            float4 v = __ldg(&lp4[j * 32 + lane]);
            s[4 * j + 0] = orderable(v.x + gumbel_from_bits(bits[4 * j + 0]));
            s[4 * j + 1] = orderable(v.y + gumbel_from_bits(bits[4 * j + 1]));
            s[4 * j + 2] = orderable(v.z + gumbel_from_bits(bits[4 * j + 2]));
            s[4 * j + 3] = orderable(v.w + gumbel_from_bits(bits[4 * j + 3]));
        }
        selm = select32(s, orderable(g_pivot[p]), lane);
    }

    write_row(out, x, b, row, selm, lane);
}

extern "C" void kernel_launch(void* const* d_in, const int* in_sizes, int n_in,
                              void* d_out, int out_size) {
    const float* x = nullptr;
    const float* w = nullptr;
    for (int i = 0; i < n_in; ++i) {
        if (in_sizes[i] == NB * NF) x = (const float*)d_in[i];
        else if (in_sizes[i] == NP * NF) w = (const float*)d_in[i];
    }
    float* out = (float*)d_out;

    prep_kernel<<<NP, NF>>>(w);
    main_kernel<<<NROWS / 8, 256>>>(x, out);
}

// round 8
// speedup vs baseline: 1.8786x; 1.0040x over previous
#include <cuda_runtime.h>

// ProbabilisticPatching: Gumbel-top-k (k=32) over 512 features per (batch,patch) row.
// RNG: JAX threefry PARTITIONABLE path: bits32[i] = xor-halves of tf2x32(key=0,(0,i)).
// R7 = R5 + cipher adds forced onto the FMA pipe via inline-PTX mad.lo.u32 (runtime
//      `one` multiplier, 16 independent chains/thread hide cross-pipe latency) and
//      pre-shifted saturated thresholds. Output bit-identical to R5.

#define NP 64
#define NF 512
#define NB 2048
#define NROWS (NB * NP)   // 131072
#define CAP 96            // per-warp candidate buffer capacity

__device__ float    g_logp [NP * NF];
__device__ unsigned g_thr9 [NP * NF];   // (thr<<9) saturated; candidate iff bits >= thr9
__device__ float    g_pivot[NP];

// mad.lo on the FMA pipe; `one`==1 at runtime, opaque to ptxas.
#define MADD(d, a, b) \
    asm("mad.lo.u32 %0, %1, %2, %3;" : "=r"(d) : "r"(a), "r"(one), "r"(b))

// ---------------- Threefry-2x32, key = (0,0); adds on FMA pipe ----------------
__device__ __forceinline__ unsigned tf_bits32(unsigned i, unsigned one) {
    const unsigned ks2  = 0x1BD11BDAu;
    const unsigned ks2a = ks2 + 1u;   // injections (compile-time consts)
    const unsigned ks2b = ks2 + 4u;
    unsigned x0, x1;
    // round 1 simplified: x0 = 0 + i
    x0 = i;
    x1 = __funnelshift_l(i, i, 13); x1 ^= x0;
#define TF_RND(r) { MADD(x0, x0, x1); x1 = __funnelshift_l(x1, x1, r); x1 ^= x0; }
    TF_RND(15) TF_RND(26) TF_RND(6)
    /* x0 += ks1(0) */            MADD(x1, x1, ks2a);        // x1 += ks2 + 1
    TF_RND(17) TF_RND(29) TF_RND(16) TF_RND(24)
    MADD(x0, x0, ks2);            MADD(x1, x1, 2u);
    TF_RND(13) TF_RND(15) TF_RND(26) TF_RND(6)
    /* x0 += ks0(0) */            MADD(x1, x1, 3u);
    TF_RND(17) TF_RND(29) TF_RND(16) TF_RND(24)
    /* x0 += ks1(0) */            MADD(x1, x1, ks2b);        // x1 += ks2 + 4
    TF_RND(13) TF_RND(15) TF_RND(26) TF_RND(6)
    MADD(x0, x0, ks2);            MADD(x1, x1, 5u);
#undef TF_RND
    return x0 ^ x1;
}

// order-preserving float -> uint mapping
__device__ __forceinline__ unsigned orderable(float f) {
    unsigned b = __float_as_uint(f);
    unsigned m = (unsigned)(((int)b) >> 31) | 0x80000000u;
    return b ^ m;
}

// JAX uniform(1e-20, 1) from raw bits, then standard Gumbel (accurate logf).
__device__ __forceinline__ float gumbel_from_bits(unsigned bits) {
    float f = __uint_as_float((bits >> 9) | 0x3f800000u) - 1.0f;
    float u = (f > 0.0f) ? f : 1e-20f;
    return -logf(-logf(u));
}

__device__ __forceinline__ float gumbel_from_m23(unsigned m23) {
    float f = __uint_as_float(m23 | 0x3f800000u) - 1.0f;
    float u = (f > 0.0f) ? f : 1e-20f;
    return -logf(-logf(u));
}

// ---------------- prep: logp (IDENTICAL math to R3) + pivot + per-f bit thresholds ----
__global__ void prep_kernel(const float* __restrict__ w) {
    int p = blockIdx.x;
    int t = threadIdx.x;
    int lane = t & 31, wid = t >> 5;
    float wv = w[p * NF + t];

    __shared__ float sm[16];
    __shared__ float ws[16];
    __shared__ float s_total;
    __shared__ float red[16];

    // exact row max (order-independent)
    float m = wv;
    for (int off = 16; off; off >>= 1)
        m = fmaxf(m, __shfl_xor_sync(0xffffffffu, m, off));
    if (lane == 0) sm[wid] = m;
    __syncthreads();
    float mall = sm[0];
    #pragma unroll
    for (int i = 1; i < 16; ++i) mall = fmaxf(mall, sm[i]);

    // sum(exp(shifted)) — DO NOT CHANGE ORDER (fixes passing rel_err)
    float e = expf(wv - mall);
    float v = e;
    v += __shfl_down_sync(0xffffffffu, v, 16);
    v += __shfl_down_sync(0xffffffffu, v, 8);
    v += __shfl_down_sync(0xffffffffu, v, 4);
    v += __shfl_down_sync(0xffffffffu, v, 2);
    v += __shfl_down_sync(0xffffffffu, v, 1);
    if (lane == 0) ws[wid] = v;
    __syncthreads();
    if (wid == 0) {
        float vv = (lane < 16) ? ws[lane] : 0.0f;
        vv += __shfl_down_sync(0xffffffffu, vv, 8);
        vv += __shfl_down_sync(0xffffffffu, vv, 4);
        vv += __shfl_down_sync(0xffffffffu, vv, 2);
        vv += __shfl_down_sync(0xffffffffu, vv, 1);
        if (lane == 0) s_total = vv;
    }
    __syncthreads();

    float L  = logf(s_total);
    float lp = (wv - mall) - L;
    g_logp[p * NF + t] = lp;

    // pivot: solve sum_f P(lp_f + G > piv) = 50 (candidate pool; mask pivot-independent)
    float lo = -40.0f, hi = 40.0f;
    for (int it = 0; it < 35; ++it) {
        float mid = 0.5f * (lo + hi);
        float pr = 1.0f - expf(-expf(lp - mid));
        float sv = pr;
        for (int off = 16; off; off >>= 1)
            sv += __shfl_xor_sync(0xffffffffu, sv, off);
        if (lane == 0) red[wid] = sv;
        __syncthreads();
        float tot = 0.0f;
        #pragma unroll
        for (int i = 0; i < 16; ++i) tot += red[i];
        __syncthreads();
        if (tot > 50.0f) lo = mid; else hi = mid;
    }
    float pivot = 0.5f * (lo + hi);   // identical in every thread

    // exact integer threshold: smallest M in [0, 2^23] with lp + g(M) > pivot.
    unsigned tlo = 0u, thi = 1u << 23;
    while (tlo < thi) {
        unsigned mid = (tlo + thi) >> 1;
        if (lp + gumbel_from_m23(mid) > pivot) thi = mid; else tlo = mid + 1;
    }
    // pre-shift: candidate iff bits >= (tlo<<9). tlo == 2^23 would overflow ->
    // saturate; only effect is a ~2^-32 false-positive *candidate* (scored exactly).
    unsigned long long t9 = (unsigned long long)tlo << 9;
    g_thr9[p * NF + t] = (t9 > 0xFFFFFFFFull) ? 0xFFFFFFFFu : (unsigned)t9;
    if (t == 0) g_pivot[p] = pivot;
}

// ---------------- exact iterative selection (FALLBACK only, ~0.3% of rows) ----------
__device__ __forceinline__ unsigned select32(const unsigned s[16], unsigned piv,
                                             unsigned lane) {
    unsigned m = 0;
    int cnt = 0;
    #pragma unroll
    for (int t = 0; t < 16; ++t) {
        if (s[t] > piv) { m |= 1u << t; ++cnt; }
    }
    cnt = __reduce_add_sync(0xffffffffu, cnt);

    if (cnt > 32) {
        for (int it = cnt; it > 32; --it) {
            unsigned long long key = ~0ull;
            #pragma unroll
            for (int t = 0; t < 16; ++t) {
                if (m & (1u << t)) {
                    unsigned f = ((unsigned)(t >> 2) << 7) + (lane << 2) + (t & 3);
                    unsigned long long k =
                        ((unsigned long long)s[t] << 32) | (511u - f);
                    key = (k < key) ? k : key;
                }
            }
            for (int off = 16; off; off >>= 1) {
                unsigned long long o = __shfl_xor_sync(0xffffffffu, key, off);
                key = (o < key) ? o : key;
            }
            unsigned f = 511u - (unsigned)(key & 0xffffffffu);
            if (((f >> 2) & 31u) == lane)
                m &= ~(1u << (((f >> 7) << 2) | (f & 3)));
        }
    } else if (cnt < 32) {
        for (int it = cnt; it < 32; ++it) {
            unsigned long long key = 0ull;
            #pragma unroll
            for (int t = 0; t < 16; ++t) {
                if (!(m & (1u << t))) {
                    unsigned f = ((unsigned)(t >> 2) << 7) + (lane << 2) + (t & 3);
                    unsigned long long k =
                        ((unsigned long long)s[t] << 32) | (511u - f);
                    key = (k > key) ? k : key;
                }
            }
            for (int off = 16; off; off >>= 1) {
                unsigned long long o = __shfl_xor_sync(0xffffffffu, key, off);
                key = (o > key) ? o : key;
            }
            unsigned f = 511u - (unsigned)(key & 0xffffffffu);
            if (((f >> 2) & 31u) == lane)
                m |= 1u << (((f >> 7) << 2) | (f & 3));
        }
    }
    return m;
}

__device__ __forceinline__ void write_row(float* __restrict__ out,
                                          const float* __restrict__ x,
                                          unsigned brow, unsigned row,
                                          unsigned m, unsigned lane) {
    const float4* x4 = reinterpret_cast<const float4*>(x + (size_t)brow * NF);
    float4* po = reinterpret_cast<float4*>(out + (size_t)row * 1024);
    float4* mo = reinterpret_cast<float4*>(out + (size_t)row * 1024 + 512);
    #pragma unroll
    for (int j = 0; j < 4; ++j) {
        float4 xv = x4[j * 32 + lane];
        int t0 = 4 * j;
        float m0 = (m >> (t0 + 0)) & 1 ? 1.0f : 0.0f;
        float m1 = (m >> (t0 + 1)) & 1 ? 1.0f : 0.0f;
        float m2 = (m >> (t0 + 2)) & 1 ? 1.0f : 0.0f;
        float m3 = (m >> (t0 + 3)) & 1 ? 1.0f : 0.0f;
        float4 pv = make_float4(xv.x * m0, xv.y * m1, xv.z * m2, xv.w * m3);
        float4 mv = make_float4(m0, m1, m2, m3);
        po[j * 32 + lane] = pv;
        mo[j * 32 + lane] = mv;
    }
}

// One warp per output row. Lane k owns f = 128j + 4k + c (t = 4j + c).
__global__ void __launch_bounds__(256, 3)
main_kernel(const float* __restrict__ x, float* __restrict__ out, unsigned one) {
    __shared__ unsigned long long keys[8][CAP];
    __shared__ unsigned wmask[8][32];

    unsigned w    = threadIdx.x >> 5;
    unsigned lane = threadIdx.x & 31u;
    unsigned row  = blockIdx.x * 8u + w;    // 0..131071
    unsigned p = row & 63u;
    unsigned b = row >> 6;
    unsigned base = row * NF;               // < 2^26
    unsigned ltmask = (1u << lane) - 1u;

    // thresholds, same f-pattern as write layout
    const uint4* th4 = reinterpret_cast<const uint4*>(g_thr9 + p * NF);
    unsigned thr[16];
    #pragma unroll
    for (int j = 0; j < 4; ++j) {
        uint4 v = __ldg(&th4[j * 32 + lane]);
        thr[4 * j + 0] = v.x; thr[4 * j + 1] = v.y;
        thr[4 * j + 2] = v.z; thr[4 * j + 3] = v.w;
    }

    // ---- phase 1: generate bits, mark candidates (no logf) ----
    unsigned bits[16];
    unsigned candm = 0;
    #pragma unroll
    for (int t = 0; t < 16; ++t) {
        unsigned f = ((unsigned)(t >> 2) << 7) + (lane << 2) + (t & 3);
        bits[t] = tf_bits32(base + f, one);
        if (bits[t] >= thr[t]) candm |= 1u << t;
    }

    // ---- compaction: ballot/prefix -> per-warp smem (bits, f) entries ----
    unsigned n = 0;
    #pragma unroll
    for (int t = 0; t < 16; ++t) {
        unsigned bal = __ballot_sync(0xffffffffu, (candm >> t) & 1u);
        if ((candm >> t) & 1u) {
            unsigned slot = n + __popc(bal & ltmask);
            unsigned f = ((unsigned)(t >> 2) << 7) + (lane << 2) + (t & 3);
            if (slot < CAP)
                keys[w][slot] = ((unsigned long long)bits[t] << 32) | f;
        }
        n += __popc(bal);
    }
    __syncwarp();

    unsigned selm;
    if (n >= 32 && n <= CAP) {
        // ---- phase 2: score only compacted candidates (<=3 per lane) ----
        for (unsigned si = lane; si < n; si += 32) {
            unsigned long long e = keys[w][si];
            unsigned bv = (unsigned)(e >> 32);
            unsigned f  = (unsigned)(e & 0x3ffu);
            float lpv = __ldg(&g_logp[p * NF + f]);
            unsigned sc = orderable(lpv + gumbel_from_bits(bv));
            keys[w][si] = ((unsigned long long)sc << 32) | (511u - f);
        }
        wmask[w][lane] = 0u;
        __syncwarp();

        // ---- phase 3: exact rank among candidates; keep rank < 32 ----
        for (unsigned si = lane; si < n; si += 32) {
            unsigned long long k = keys[w][si];
            int rank = 0;
            for (unsigned j = 0; j < n; ++j)
                rank += (keys[w][j] > k) ? 1 : 0;
            if (rank < 32) {
                unsigned f = 511u - (unsigned)(k & 0x3ffu);
                unsigned owner = (f >> 2) & 31u;
                unsigned bit = ((f >> 7) << 2) | (f & 3u);
                atomicOr(&wmask[w][owner], 1u << bit);
            }
        }
        __syncwarp();
        selm = wmask[w][lane];
    } else {
        // ---- fallback (~0.3%): full scores + exact iterative select ----
        const float4* lp4 = reinterpret_cast<const float4*>(g_logp + p * NF);
        unsigned s[16];
        #pragma unroll
        for (int j = 0; j < 4; ++j) {
            float4 v = __ldg(&lp4[j * 32 + lane]);
            s[4 * j + 0] = orderable(v.x + gumbel_from_bits(bits[4 * j + 0]));
            s[4 * j + 1] = orderable(v.y + gumbel_from_bits(bits[4 * j + 1]));
            s[4 * j + 2] = orderable(v.z + gumbel_from_bits(bits[4 * j + 2]));
            s[4 * j + 3] = orderable(v.w + gumbel_from_bits(bits[4 * j + 3]));
        }
        selm = select32(s, orderable(g_pivot[p]), lane);
    }

    write_row(out, x, b, row, selm, lane);
}

extern "C" void kernel_launch(void* const* d_in, const int* in_sizes, int n_in,
                              void* d_out, int out_size) {
    const float* x = nullptr;
    const float* w = nullptr;
    for (int i = 0; i < n_in; ++i) {
        if (in_sizes[i] == NB * NF) x = (const float*)d_in[i];
        else if (in_sizes[i] == NP * NF) w = (const float*)d_in[i];
    }
    float* out = (float*)d_out;

    prep_kernel<<<NP, NF>>>(w);
    main_kernel<<<NROWS / 8, 256>>>(x, out, 1u);
}

// round 9
// speedup vs baseline: 1.9719x; 1.0497x over previous
#include <cuda_runtime.h>

// ProbabilisticPatching: Gumbel-top-k (k=32) over 512 features per (batch,patch) row.
// RNG: JAX threefry PARTITIONABLE path: bits32[i] = xor-halves of tf2x32(key=0,(0,i)).
// R9: issue-bound shaves — fused generate/ballot/compact (no bits[] array; fallback
//     regenerates), fused multi-entry rank loop, 64-reg / 4-block occupancy target.
//     Mask stream bit-identical to R5/R7.

#define NP 64
#define NF 512
#define NB 2048
#define NROWS (NB * NP)   // 131072
#define CAP 96            // per-warp candidate buffer capacity

__device__ float    g_logp [NP * NF];
__device__ unsigned g_thr9 [NP * NF];   // (thr<<9) saturated; candidate iff bits >= thr9
__device__ float    g_pivot[NP];

// ---------------- Threefry-2x32, key = (0,0) ----------------
__device__ __forceinline__ unsigned tf_bits32(unsigned i) {
    const unsigned ks2 = 0x1BD11BDAu;
    unsigned x0 = i;                               // round 1: x0 = 0 + i
    unsigned x1 = __funnelshift_l(i, i, 13) ^ x0;
#define TF_RND(r) { x0 += x1; x1 = __funnelshift_l(x1, x1, r) ^ x0; }
    TF_RND(15) TF_RND(26) TF_RND(6)
    /* x0 += ks1(0) */            x1 += ks2 + 1u;
    TF_RND(17) TF_RND(29) TF_RND(16) TF_RND(24)
    x0 += ks2;                    x1 += 2u;
    TF_RND(13) TF_RND(15) TF_RND(26) TF_RND(6)
    /* x0 += ks0(0) */            x1 += 3u;
    TF_RND(17) TF_RND(29) TF_RND(16) TF_RND(24)
    /* x0 += ks1(0) */            x1 += ks2 + 4u;
    TF_RND(13) TF_RND(15) TF_RND(26) TF_RND(6)
    x0 += ks2;                    x1 += 5u;
#undef TF_RND
    return x0 ^ x1;
}

// order-preserving float -> uint mapping
__device__ __forceinline__ unsigned orderable(float f) {
    unsigned b = __float_as_uint(f);
    unsigned m = (unsigned)(((int)b) >> 31) | 0x80000000u;
    return b ^ m;
}

// JAX uniform(1e-20, 1) from raw bits, then standard Gumbel (accurate logf).
__device__ __forceinline__ float gumbel_from_bits(unsigned bits) {
    float f = __uint_as_float((bits >> 9) | 0x3f800000u) - 1.0f;
    float u = (f > 0.0f) ? f : 1e-20f;
    return -logf(-logf(u));
}

__device__ __forceinline__ float gumbel_from_m23(unsigned m23) {
    float f = __uint_as_float(m23 | 0x3f800000u) - 1.0f;
    float u = (f > 0.0f) ? f : 1e-20f;
    return -logf(-logf(u));
}

// ---------------- prep: logp (IDENTICAL math to R3) + pivot + per-f bit thresholds ----
__global__ void prep_kernel(const float* __restrict__ w) {
    int p = blockIdx.x;
    int t = threadIdx.x;
    int lane = t & 31, wid = t >> 5;
    float wv = w[p * NF + t];

    __shared__ float sm[16];
    __shared__ float ws[16];
    __shared__ float s_total;
    __shared__ float red[16];

    // exact row max (order-independent)
    float m = wv;
    for (int off = 16; off; off >>= 1)
        m = fmaxf(m, __shfl_xor_sync(0xffffffffu, m, off));
    if (lane == 0) sm[wid] = m;
    __syncthreads();
    float mall = sm[0];
    #pragma unroll
    for (int i = 1; i < 16; ++i) mall = fmaxf(mall, sm[i]);

    // sum(exp(shifted)) — DO NOT CHANGE ORDER (fixes passing rel_err)
    float e = expf(wv - mall);
    float v = e;
    v += __shfl_down_sync(0xffffffffu, v, 16);
    v += __shfl_down_sync(0xffffffffu, v, 8);
    v += __shfl_down_sync(0xffffffffu, v, 4);
    v += __shfl_down_sync(0xffffffffu, v, 2);
    v += __shfl_down_sync(0xffffffffu, v, 1);
    if (lane == 0) ws[wid] = v;
    __syncthreads();
    if (wid == 0) {
        float vv = (lane < 16) ? ws[lane] : 0.0f;
        vv += __shfl_down_sync(0xffffffffu, vv, 8);
        vv += __shfl_down_sync(0xffffffffu, vv, 4);
        vv += __shfl_down_sync(0xffffffffu, vv, 2);
        vv += __shfl_down_sync(0xffffffffu, vv, 1);
        if (lane == 0) s_total = vv;
    }
    __syncthreads();

    float L  = logf(s_total);
    float lp = (wv - mall) - L;
    g_logp[p * NF + t] = lp;

    // pivot: solve sum_f P(lp_f + G > piv) = 50 (candidate pool; mask pivot-independent)
    float lo = -40.0f, hi = 40.0f;
    for (int it = 0; it < 35; ++it) {
        float mid = 0.5f * (lo + hi);
        float pr = 1.0f - expf(-expf(lp - mid));
        float sv = pr;
        for (int off = 16; off; off >>= 1)
            sv += __shfl_xor_sync(0xffffffffu, sv, off);
        if (lane == 0) red[wid] = sv;
        __syncthreads();
        float tot = 0.0f;
        #pragma unroll
        for (int i = 0; i < 16; ++i) tot += red[i];
        __syncthreads();
        if (tot > 50.0f) lo = mid; else hi = mid;
    }
    float pivot = 0.5f * (lo + hi);   // identical in every thread

    // exact integer threshold: smallest M in [0, 2^23] with lp + g(M) > pivot.
    unsigned tlo = 0u, thi = 1u << 23;
    while (tlo < thi) {
        unsigned mid = (tlo + thi) >> 1;
        if (lp + gumbel_from_m23(mid) > pivot) thi = mid; else tlo = mid + 1;
    }
    // pre-shift: candidate iff bits >= (tlo<<9); overflow saturates (adds at most a
    // ~2^-32 false-positive candidate, which exact scoring ranks correctly).
    unsigned long long t9 = (unsigned long long)tlo << 9;
    g_thr9[p * NF + t] = (t9 > 0xFFFFFFFFull) ? 0xFFFFFFFFu : (unsigned)t9;
    if (t == 0) g_pivot[p] = pivot;
}

// ---------------- exact iterative selection (FALLBACK only, ~0.5% of rows) ----------
__device__ __forceinline__ unsigned select32(const unsigned s[16], unsigned piv,
                                             unsigned lane) {
    unsigned m = 0;
    int cnt = 0;
    #pragma unroll
    for (int t = 0; t < 16; ++t) {
        if (s[t] > piv) { m |= 1u << t; ++cnt; }
    }
    cnt = __reduce_add_sync(0xffffffffu, cnt);

    if (cnt > 32) {
        for (int it = cnt; it > 32; --it) {
            unsigned long long key = ~0ull;
            #pragma unroll
            for (int t = 0; t < 16; ++t) {
                if (m & (1u << t)) {
                    unsigned f = ((unsigned)(t >> 2) << 7) + (lane << 2) + (t & 3);
                    unsigned long long k =
                        ((unsigned long long)s[t] << 32) | (511u - f);
                    key = (k < key) ? k : key;
                }
            }
            for (int off = 16; off; off >>= 1) {
                unsigned long long o = __shfl_xor_sync(0xffffffffu, key, off);
                key = (o < key) ? o : key;
            }
            unsigned f = 511u - (unsigned)(key & 0xffffffffu);
            if (((f >> 2) & 31u) == lane)
                m &= ~(1u << (((f >> 7) << 2) | (f & 3)));
        }
    } else if (cnt < 32) {
        for (int it = cnt; it < 32; ++it) {
            unsigned long long key = 0ull;
            #pragma unroll
            for (int t = 0; t < 16; ++t) {
                if (!(m & (1u << t))) {
                    unsigned f = ((unsigned)(t >> 2) << 7) + (lane << 2) + (t & 3);
                    unsigned long long k =
                        ((unsigned long long)s[t] << 32) | (511u - f);
                    key = (k > key) ? k : key;
                }
            }
            for (int off = 16; off; off >>= 1) {
                unsigned long long o = __shfl_xor_sync(0xffffffffu, key, off);
                key = (o > key) ? o : key;
            }
            unsigned f = 511u - (unsigned)(key & 0xffffffffu);
            if (((f >> 2) & 31u) == lane)
                m |= 1u << (((f >> 7) << 2) | (f & 3));
        }
    }
    return m;
}

__device__ __forceinline__ void write_row(float* __restrict__ out,
                                          const float* __restrict__ x,
                                          unsigned brow, unsigned row,
                                          unsigned m, unsigned lane) {
    const float4* x4 = reinterpret_cast<const float4*>(x + (size_t)brow * NF);
    float4* po = reinterpret_cast<float4*>(out + (size_t)row * 1024);
    float4* mo = reinterpret_cast<float4*>(out + (size_t)row * 1024 + 512);
    #pragma unroll
    for (int j = 0; j < 4; ++j) {
        float4 xv = x4[j * 32 + lane];
        int t0 = 4 * j;
        float m0 = (m >> (t0 + 0)) & 1 ? 1.0f : 0.0f;
        float m1 = (m >> (t0 + 1)) & 1 ? 1.0f : 0.0f;
        float m2 = (m >> (t0 + 2)) & 1 ? 1.0f : 0.0f;
        float m3 = (m >> (t0 + 3)) & 1 ? 1.0f : 0.0f;
        float4 pv = make_float4(xv.x * m0, xv.y * m1, xv.z * m2, xv.w * m3);
        float4 mv = make_float4(m0, m1, m2, m3);
        po[j * 32 + lane] = pv;
        mo[j * 32 + lane] = mv;
    }
}

// One warp per output row. Lane k owns f = 128j + 4k + c (t = 4j + c).
__global__ void __launch_bounds__(256, 4)
main_kernel(const float* __restrict__ x, float* __restrict__ out) {
    __shared__ unsigned long long keys[8][CAP];
    __shared__ unsigned wmask[8][32];

    unsigned w    = threadIdx.x >> 5;
    unsigned lane = threadIdx.x & 31u;
    unsigned row  = blockIdx.x * 8u + w;    // 0..131071
    unsigned p = row & 63u;
    unsigned b = row >> 6;
    unsigned base = row * NF;               // < 2^26
    unsigned ltmask = (1u << lane) - 1u;

    // thresholds, same f-pattern as write layout
    const uint4* th4 = reinterpret_cast<const uint4*>(g_thr9 + p * NF);
    unsigned thr[16];
    #pragma unroll
    for (int j = 0; j < 4; ++j) {
        uint4 v = __ldg(&th4[j * 32 + lane]);
        thr[4 * j + 0] = v.x; thr[4 * j + 1] = v.y;
        thr[4 * j + 2] = v.z; thr[4 * j + 3] = v.w;
    }

    // ---- fused: generate bits -> compare -> ballot -> compact store (no bits[]) ----
    unsigned n = 0;
    #pragma unroll
    for (int t = 0; t < 16; ++t) {
        unsigned f = ((unsigned)(t >> 2) << 7) + (lane << 2) + (t & 3);
        unsigned bt = tf_bits32(base + f);
        bool c = (bt >= thr[t]);
        unsigned bal = __ballot_sync(0xffffffffu, c);
        if (c) {
            unsigned slot = n + __popc(bal & ltmask);
            if (slot < CAP)
                keys[w][slot] = ((unsigned long long)bt << 32) | f;
        }
        n += __popc(bal);
    }
    __syncwarp();

    unsigned selm;
    if (n >= 32 && n <= CAP) {
        // ---- score compacted candidates (<=3 per lane); scored key replaces entry --
        for (unsigned si = lane; si < n; si += 32) {
            unsigned long long e = keys[w][si];
            unsigned bv = (unsigned)(e >> 32);
            unsigned f  = (unsigned)(e & 0x3ffu);
            float lpv = __ldg(&g_logp[p * NF + f]);
            unsigned sc = orderable(lpv + gumbel_from_bits(bv));
            keys[w][si] = ((unsigned long long)sc << 32) | (511u - f);
        }
        wmask[w][lane] = 0u;
        __syncwarp();

        // ---- fused exact rank: one LDS per key serves all of this lane's entries --
        unsigned long long e0 = keys[w][lane];
        bool has1 = (32u + lane) < n;
        bool has2 = (64u + lane) < n;
        unsigned long long e1 = has1 ? keys[w][32u + lane] : 0ull;
        int r0 = 0, r1 = 0, r2 = 0;
        if (!has2) {                      // n <= 64 (common)
            for (unsigned j = 0; j < n; ++j) {
                unsigned long long kk = keys[w][j];
                r0 += (kk > e0) ? 1 : 0;
                r1 += (kk > e1) ? 1 : 0;
            }
        } else {                          // 64 < n <= 96 (rare, ~2%)
            unsigned long long e2 = keys[w][64u + lane];
            for (unsigned j = 0; j < n; ++j) {
                unsigned long long kk = keys[w][j];
                r0 += (kk > e0) ? 1 : 0;
                r1 += (kk > e1) ? 1 : 0;
                r2 += (kk > e2) ? 1 : 0;
            }
            if (r2 < 32) {
                unsigned f = 511u - (unsigned)(e2 & 0x3ffu);
                atomicOr(&wmask[w][(f >> 2) & 31u],
                         1u << (((f >> 7) << 2) | (f & 3u)));
            }
        }
        if (r0 < 32) {
            unsigned f = 511u - (unsigned)(e0 & 0x3ffu);
            atomicOr(&wmask[w][(f >> 2) & 31u],
                     1u << (((f >> 7) << 2) | (f & 3u)));
        }
        if (has1 && r1 < 32) {
            unsigned f = 511u - (unsigned)(e1 & 0x3ffu);
            atomicOr(&wmask[w][(f >> 2) & 31u],
                     1u << (((f >> 7) << 2) | (f & 3u)));
        }
        __syncwarp();
        selm = wmask[w][lane];
    } else {
        // ---- fallback (~0.5%): regenerate bits, full scores, exact iterative select -
        const float4* lp4 = reinterpret_cast<const float4*>(g_logp + p * NF);
        unsigned s[16];
        #pragma unroll
        for (int j = 0; j < 4; ++j) {
            float4 v = __ldg(&lp4[j * 32 + lane]);
            unsigned f0 = ((unsigned)j << 7) + (lane << 2);
            s[4 * j + 0] = orderable(v.x + gumbel_from_bits(tf_bits32(base + f0 + 0)));
            s[4 * j + 1] = orderable(v.y + gumbel_from_bits(tf_bits32(base + f0 + 1)));
            s[4 * j + 2] = orderable(v.z + gumbel_from_bits(tf_bits32(base + f0 + 2)));
            s[4 * j + 3] = orderable(v.w + gumbel_from_bits(tf_bits32(base + f0 + 3)));
        }
        selm = select32(s, orderable(g_pivot[p]), lane);
    }

    write_row(out, x, b, row, selm, lane);
}

extern "C" void kernel_launch(void* const* d_in, const int* in_sizes, int n_in,
                              void* d_out, int out_size) {
    const float* x = nullptr;
    const float* w = nullptr;
    for (int i = 0; i < n_in; ++i) {
        if (in_sizes[i] == NB * NF) x = (const float*)d_in[i];
        else if (in_sizes[i] == NP * NF) w = (const float*)d_in[i];
    }
    float* out = (float*)d_out;

    prep_kernel<<<NP, NF>>>(w);
    main_kernel<<<NROWS / 8, 256>>>(x, out);
}